// round 9
// baseline (speedup 1.0000x reference)
#include <cuda_runtime.h>

#define NT 128
#define BB 256
#define SS 512

// global accumulator (double, zeroed at the start of every launch -> graph-replay safe)
__device__ double g_acc;
__device__ int    g_tags_is64;

__global__ void zero_acc_kernel(){ g_acc = 0.0; }
__global__ void fin_kernel(float* out){ out[0] = (float)g_acc; }

// Detect tags dtype: if interpreted as int64, all high words of valid tags
// (0..127) are zero. Genuine int32 tags have nonzero odd words a.s.
__global__ void detect_tags_kernel(const int* tags32){
    __shared__ int nz;
    if (threadIdx.x == 0) nz = 0;
    __syncthreads();
    int c = 0;
    for (int k = threadIdx.x; k < 2048; k += 256)
        if (tags32[2 * k + 1] != 0) c = 1;
    if (c) atomicOr(&nz, 1);
    __syncthreads();
    if (threadIdx.x == 0) g_tags_is64 = (nz == 0) ? 1 : 0;
}

// gold = sum_{b,t} emis[b,t,tag[b,t]]*m[b,t] + sum_{b,t>=1} trans[tag[b,t-1],tag[b,t]]*m[b,t]
__global__ void __launch_bounds__(256) gold_kernel(
    const float* __restrict__ emis, const void* __restrict__ tags_raw,
    const unsigned char* __restrict__ mask, const float* __restrict__ trans)
{
    const int idx = blockIdx.x * 256 + threadIdx.x;   // 0 .. B*S-1
    const int t = idx & (SS - 1);
    const int is64 = g_tags_is64;
    const int* t32 = (const int*)tags_raw;
    const long long* t64 = (const long long*)tags_raw;

    const int tg = is64 ? (int)t64[idx] : t32[idx];
    const float m = mask[idx] ? 1.f : 0.f;
    float v = emis[(size_t)idx * NT + tg] * m;
    if (t > 0){
        const int tp = is64 ? (int)t64[idx - 1] : t32[idx - 1];
        v += trans[tp * NT + tg] * m;
    }
    #pragma unroll
    for (int off = 16; off >= 1; off >>= 1)
        v += __shfl_xor_sync(0xffffffffu, v, off);
    if ((threadIdx.x & 31) == 0)
        atomicAdd(&g_acc, -(double)v);
}

// Forward algorithm, linear domain with exact periodic rescaling.
// 128 blocks x 256 threads. Block handles 2 independent chains:
//   half h = tid>>7 (chain b = 2*blk + h), tag j = tid&127.
// Thread j keeps exp(T[:, j]) (128 floats) in registers and computes the full
// 128-term dot product itself (4-way ILP). No cross-thread reduction for the dot.
__global__ void __launch_bounds__(256, 1) crf_forward(
    const float* __restrict__ emis, const float* __restrict__ trans)
{
    __shared__ __align__(16) float alpha[2][2][NT];  // [parity][half][tag]
    __shared__ float wmax[8];                        // per-warp maxes (4 per half)

    const int tid  = threadIdx.x;
    const int h    = tid >> 7;
    const int j    = tid & 127;
    const int w    = tid >> 5;          // warp 0..7 (0-3 half0, 4-7 half1)
    const int lane = tid & 31;
    const int b    = blockIdx.x * 2 + h;

    // register-cached exp(transitions) column j
    float eT[NT];
    #pragma unroll
    for (int i = 0; i < NT; i++)
        eT[i] = __expf(trans[i * NT + j]);

    const float* eb = emis + (size_t)b * SS * NT + j;

    // alpha_0 = exp(e_0)
    const float a0 = __expf(eb[0]);
    alpha[0][h][j] = a0;
    {
        float mx = a0;
        #pragma unroll
        for (int off = 16; off >= 1; off >>= 1)
            mx = fmaxf(mx, __shfl_xor_sync(0xffffffffu, mx, off));
        if (lane == 0) wmax[w] = mx;
    }

    float eraw = eb[NT];                // raw emission for t = 1 (prefetched)
    __syncthreads();

    float lz = 0.f;                     // uniform within a half

    for (int t = 1; t < SS; t++){
        const int p = t & 1;
        const float ecur = eraw;
        if (t + 1 < SS) eraw = eb[(size_t)(t + 1) * NT];   // prefetch next step

        // full dot: acc = sum_i alpha[t-1][i] * exp(T[i][j]), 4 ILP chains
        float c0 = 0.f, c1 = 0.f, c2 = 0.f, c3 = 0.f;
        const float4* ap = (const float4*)alpha[p ^ 1][h];   // broadcast reads
        #pragma unroll
        for (int k = 0; k < NT / 4; k++){
            const float4 a = ap[k];
            c0 = fmaf(a.x, eT[4 * k + 0], c0);
            c1 = fmaf(a.y, eT[4 * k + 1], c1);
            c2 = fmaf(a.z, eT[4 * k + 2], c2);
            c3 = fmaf(a.w, eT[4 * k + 3], c3);
        }
        const float acc = (c0 + c1) + (c2 + c3);

        // consume rescale max (produced at step t-1 when (t-1)%4 == 0)
        float inv = 1.f;
        if (((t - 1) & 3) == 0){
            const float* wm = wmax + 4 * h;
            const float m = fmaxf(fmaxf(wm[0], wm[1]), fmaxf(wm[2], wm[3]));
            inv = 1.0f / m;
            lz += logf(m);              // exact compensation of the divide
        }

        const float v = acc * inv * __expf(ecur);

        // produce max for the rescale at step t+1
        if ((t & 3) == 0){
            float mx = v;
            #pragma unroll
            for (int off = 16; off >= 1; off >>= 1)
                mx = fmaxf(mx, __shfl_xor_sync(0xffffffffu, mx, off));
            if (lane == 0) wmax[w] = mx;
        }

        alpha[p][h][j] = v;
        __syncthreads();
    }

    // partition contribution of this chain: log(sum_j alpha_511[j]) + lz
    if (j == 0){
        double s = 0.0;
        for (int i = 0; i < NT; i++)
            s += (double)alpha[1][h][i];      // last parity: 511 & 1 = 1
        atomicAdd(&g_acc, log(s) + (double)lz);
    }
}

extern "C" void kernel_launch(void* const* d_in, const int* in_sizes, int n_in,
                              void* d_out, int out_size)
{
    const float*         emis  = (const float*)d_in[0];
    const void*          tags  = d_in[1];
    const unsigned char* mask  = (const unsigned char*)d_in[2];
    const float*         trans = (const float*)d_in[3];

    zero_acc_kernel<<<1, 1>>>();
    detect_tags_kernel<<<1, 256>>>((const int*)tags);
    gold_kernel<<<(BB * SS) / 256, 256>>>(emis, tags, mask, trans);
    crf_forward<<<BB / 2, 256>>>(emis, trans);
    fin_kernel<<<1, 1>>>((float*)d_out);
}